// round 1
// baseline (speedup 1.0000x reference)
#include <cuda_runtime.h>
#include <cstdint>
#include <cstddef>

// ---------------------------------------------------------------------------
// VQ quantizer:  z (NT x 64) vs codebook (K x 64)
// outputs (concatenated float32): e[NT], z_q[NT*64], sim[NT*K], loss[NT]
//   dot   = z . e_k
//   dist  = |z|^2 - 2 dot + |e_k|^2 ;  e = argmin_k dist
//   sim   = dot / (|z| |e_k|)
//   loss  = 1.25 * || z - z_q ||_2
// ---------------------------------------------------------------------------

#define D        64
#define BM       64     // tokens per block
#define BN       128    // codes per chunk
#define THREADS  256
#define TT       8      // tokens per thread (micro-tile)
#define TC       4      // codes per thread (micro-tile)

#define FMA2(c, a, b) \
    asm("fma.rn.f32x2 %0, %1, %2, %3;" : "=l"(c) : "l"(a), "l"(b), "l"(c))

__device__ __forceinline__ float2 unpack2(unsigned long long v) {
    float2 r;
    asm("mov.b64 {%0, %1}, %2;" : "=f"(r.x), "=f"(r.y) : "l"(v));
    return r;
}

// codebook norms (precomputed once per launch; K <= 4096)
__device__ float g_en2[4096];
__device__ float g_einv[4096];

__global__ void vq_enorm_kernel(const float* __restrict__ cbk, int K) {
    int k = blockIdx.x * blockDim.x + threadIdx.x;
    if (k >= K) return;
    const float4* row = reinterpret_cast<const float4*>(cbk + (size_t)k * D);
    float s = 0.f;
#pragma unroll
    for (int i = 0; i < D / 4; ++i) {
        float4 v = row[i];
        s += v.x * v.x + v.y * v.y + v.z * v.z + v.w * v.w;
    }
    g_en2[k]  = s;
    g_einv[k] = rsqrtf(s);
}

// dynamic smem layout:
//   zs    : BM * D floats             (16384 B)
//   es2   : (D/2) * BN  float2 pairs  (32768 B)   es2[dp][c] = (e[2dp][c], e[2dp+1][c])
//   znorm : BM floats                 (256 B)
//   zinv  : BM floats                 (256 B)
//   en2s  : BN floats                 (512 B)
//   einvs : BN floats                 (512 B)
__global__ void __launch_bounds__(THREADS, 2)
vq_main_kernel(const float* __restrict__ z,
               const float* __restrict__ cbk,
               int K,
               float* __restrict__ e_out,
               float* __restrict__ zq_out,
               float* __restrict__ sim_out,
               float* __restrict__ loss_out) {
    extern __shared__ unsigned char smem_raw[];
    float*  zs     = reinterpret_cast<float*>(smem_raw);                    // [BM][D]
    float2* es2    = reinterpret_cast<float2*>(smem_raw + BM * D * 4);      // [D/2][BN]
    float*  znorms = reinterpret_cast<float*>(smem_raw + BM * D * 4 + (D / 2) * BN * 8);
    float*  zinvs  = znorms + BM;
    float*  en2s   = zinvs + BM;
    float*  einvs  = en2s + BN;

    const int tid  = threadIdx.x;
    const int lane = tid & 31;
    const int warp = tid >> 5;
    const int t0   = warp * TT;       // local token base (this warp owns tokens t0..t0+7)
    const int c0   = lane * TC;       // chunk-local code base

    // ---- load z tile (coalesced float4) --------------------------------
    {
        const float4* zg = reinterpret_cast<const float4*>(z + (size_t)blockIdx.x * BM * D);
        float4* zsf = reinterpret_cast<float4*>(zs);
#pragma unroll
        for (int i = tid; i < BM * D / 4; i += THREADS) zsf[i] = zg[i];
    }
    __syncthreads();

    // ---- per-token norms ----------------------------------------------
    if (tid < BM) {
        const float4* row = reinterpret_cast<const float4*>(zs + tid * D);
        float s = 0.f;
#pragma unroll
        for (int i = 0; i < D / 4; ++i) {
            float4 v = row[i];
            s += v.x * v.x + v.y * v.y + v.z * v.z + v.w * v.w;
        }
        znorms[tid] = s;
        zinvs[tid]  = rsqrtf(s);
    }

    float mind[TT];
    int   mini[TT];
#pragma unroll
    for (int t = 0; t < TT; ++t) { mind[t] = 3.4e38f; mini[t] = 0; }

    const unsigned long long* zs_u = reinterpret_cast<const unsigned long long*>(zs);   // [BM][D/2]
    const unsigned long long* es_u = reinterpret_cast<const unsigned long long*>(es2);  // [D/2][BN]

    const int nchunks = K / BN;
    for (int cbi = 0; cbi < nchunks; ++cbi) {
        __syncthreads();   // previous chunk's compute done before overwriting es2

        // ---- load codebook chunk, transposed to pair-major ------------
        {
            const float* base = cbk + (size_t)cbi * BN * D;
#pragma unroll
            for (int idx = tid; idx < BN * (D / 4); idx += THREADS) {
                int q = idx & (D / 4 - 1);        // dim quad 0..15 (coalesced fastest)
                int c = idx >> 4;                 // code 0..127
                float4 v = *reinterpret_cast<const float4*>(base + (size_t)c * D + q * 4);
                es2[(2 * q) * BN + c]     = make_float2(v.x, v.y);
                es2[(2 * q + 1) * BN + c] = make_float2(v.z, v.w);
            }
            if (tid < BN) {
                en2s[tid]  = g_en2[cbi * BN + tid];
                einvs[tid] = g_einv[cbi * BN + tid];
            }
        }
        __syncthreads();

        // ---- 8x4 micro-tile, f32x2 packed FMA over the 64-dim axis ----
        unsigned long long acc[TT][TC];
#pragma unroll
        for (int t = 0; t < TT; ++t)
#pragma unroll
            for (int i = 0; i < TC; ++i) acc[t][i] = 0ull;

#pragma unroll 4
        for (int dp = 0; dp < D / 2; ++dp) {
            unsigned long long b0 = es_u[dp * BN + c0 + 0];
            unsigned long long b1 = es_u[dp * BN + c0 + 1];
            unsigned long long b2 = es_u[dp * BN + c0 + 2];
            unsigned long long b3 = es_u[dp * BN + c0 + 3];
#pragma unroll
            for (int t = 0; t < TT; ++t) {
                unsigned long long a = zs_u[(t0 + t) * (D / 2) + dp];   // warp-uniform broadcast
                FMA2(acc[t][0], a, b0);
                FMA2(acc[t][1], a, b1);
                FMA2(acc[t][2], a, b2);
                FMA2(acc[t][3], a, b3);
            }
        }

        // ---- epilogue: dist/argmin update + fused sim write -----------
#pragma unroll
        for (int t = 0; t < TT; ++t) {
            float nzv = znorms[t0 + t];
            float ziv = zinvs[t0 + t];
            float4 simv;
            float* sp = &simv.x;
#pragma unroll
            for (int i = 0; i < TC; ++i) {
                float2 p  = unpack2(acc[t][i]);
                float dot = p.x + p.y;
                int   cl  = c0 + i;
                float dist = nzv - 2.f * dot + en2s[cl];
                int   gc   = cbi * BN + cl;
                if (dist < mind[t] || (dist == mind[t] && gc < mini[t])) {
                    mind[t] = dist; mini[t] = gc;
                }
                sp[i] = dot * ziv * einvs[cl];
            }
            size_t tok = (size_t)blockIdx.x * BM + t0 + t;
            __stcs(reinterpret_cast<float4*>(sim_out + tok * (size_t)K + cbi * BN + c0), simv);
        }
    }

    // ---- argmin reduce across the warp's 32 code-lanes ----------------
#pragma unroll
    for (int t = 0; t < TT; ++t) {
        float d  = mind[t];
        int   ix = mini[t];
#pragma unroll
        for (int off = 16; off; off >>= 1) {
            float od = __shfl_xor_sync(0xffffffffu, d, off);
            int   oi = __shfl_xor_sync(0xffffffffu, ix, off);
            if (od < d || (od == d && oi < ix)) { d = od; ix = oi; }
        }
        // all lanes now agree on (d, ix)
        int    tl  = t0 + t;
        size_t tok = (size_t)blockIdx.x * BM + tl;

        // gather the winning code row cooperatively (2 dims / lane)
        float2 ev = reinterpret_cast<const float2*>(cbk + (size_t)ix * D)[lane];
        reinterpret_cast<float2*>(zq_out + tok * D)[lane] = ev;

        float2 zv = reinterpret_cast<const float2*>(zs + tl * D)[lane];
        float dx = zv.x - ev.x, dy = zv.y - ev.y;
        float s = dx * dx + dy * dy;
#pragma unroll
        for (int off = 16; off; off >>= 1) s += __shfl_xor_sync(0xffffffffu, s, off);

        if (lane == 0) {
            loss_out[tok] = 1.25f * sqrtf(s);      // codebook + 0.25*commit, same forward value
            e_out[tok]    = (float)ix;
        }
    }
}

extern "C" void kernel_launch(void* const* d_in, const int* in_sizes, int n_in,
                              void* d_out, int out_size) {
    const float* z   = (const float*)d_in[0];
    const float* cbk = (const float*)d_in[1];
    const int NT = in_sizes[0] / D;     // 131072 tokens
    const int K  = in_sizes[1] / D;     // 1024 codes

    float* out      = (float*)d_out;
    float* e_out    = out;
    float* zq_out   = e_out + NT;
    float* sim_out  = zq_out + (size_t)NT * D;
    float* loss_out = sim_out + (size_t)NT * K;

    vq_enorm_kernel<<<(K + 255) / 256, 256>>>(cbk, K);

    const size_t smem = (size_t)BM * D * 4        // zs
                      + (size_t)(D / 2) * BN * 8  // es2
                      + BM * 4 + BM * 4           // znorm, zinv
                      + BN * 4 + BN * 4;          // en2s, einvs
    cudaFuncSetAttribute(vq_main_kernel, cudaFuncAttributeMaxDynamicSharedMemorySize, (int)smem);
    vq_main_kernel<<<NT / BM, THREADS, smem>>>(z, cbk, K, e_out, zq_out, sim_out, loss_out);
}

// round 2
// speedup vs baseline: 1.5650x; 1.5650x over previous
#include <cuda_runtime.h>
#include <cstdint>
#include <cstddef>

// ---------------------------------------------------------------------------
// VQ quantizer:  z (NT x 64) vs codebook (K x 64)
// outputs (concat float32): e[NT], z_q[NT*64], sim[NT*K], loss[NT]
//   dot  = z . e_k ;  dist = |z|^2 - 2 dot + |e_k|^2 ;  e = argmin_k dist
//   sim  = dot / (|z| |e_k|) ;  loss = 1.25 * ||z - z_q||
// ---------------------------------------------------------------------------

#define D        64
#define DP       68     // padded smem row (floats): bank-conflict-free by construction
#define BM       64     // tokens per block
#define BN       128    // codes per chunk
#define THREADS  256
#define TT       8      // tokens per thread
#define TC       4      // codes per lane  (code = lane + 32*i)

#define FMA2(c, a, b) \
    asm("fma.rn.f32x2 %0, %1, %2, %3;" : "=l"(c) : "l"(a), "l"(b), "l"(c))

#define CP_ASYNC16(dst, src) \
    asm volatile("cp.async.ca.shared.global [%0], [%1], 16;" :: "r"(dst), "l"(src))
#define CP_COMMIT()  asm volatile("cp.async.commit_group;")
#define CP_WAIT0()   asm volatile("cp.async.wait_group 0;")

__device__ __forceinline__ unsigned long long pack2(float x, float y) {
    unsigned long long r;
    asm("mov.b64 %0, {%1, %2};" : "=l"(r) : "f"(x), "f"(y));
    return r;
}
__device__ __forceinline__ float2 unpack2(unsigned long long v) {
    float2 r;
    asm("mov.b64 {%0, %1}, %2;" : "=f"(r.x), "=f"(r.y) : "l"(v));
    return r;
}

// codebook norms (precomputed; K <= 4096)
__device__ float g_en2[4096];
__device__ float g_einv[4096];

__global__ void vq_enorm_kernel(const float* __restrict__ cbk, int K) {
    int k = blockIdx.x * blockDim.x + threadIdx.x;
    if (k >= K) return;
    const float4* row = reinterpret_cast<const float4*>(cbk + (size_t)k * D);
    float s = 0.f;
#pragma unroll
    for (int i = 0; i < D / 4; ++i) {
        float4 v = row[i];
        s += v.x * v.x + v.y * v.y + v.z * v.z + v.w * v.w;
    }
    g_en2[k]  = s;
    g_einv[k] = rsqrtf(s);
}

// dynamic smem layout (floats):
//   zs    : BM * DP            (17408 B)   z tile, padded rows
//   es    : BN * DP            (34816 B)   codebook chunk, padded rows, NO transpose
//   znorm : BM                 (256 B)
//   zinv  : BM                 (256 B)
//   en2s  : BN                 (512 B)
//   einvs : BN                 (512 B)
__global__ void __launch_bounds__(THREADS, 2)
vq_main_kernel(const float* __restrict__ z,
               const float* __restrict__ cbk,
               int K,
               float* __restrict__ e_out,
               float* __restrict__ zq_out,
               float* __restrict__ sim_out,
               float* __restrict__ loss_out) {
    extern __shared__ float smem[];
    float* zs     = smem;                       // [BM][DP]
    float* es     = zs + BM * DP;               // [BN][DP]
    float* znorms = es + BN * DP;
    float* zinvs  = znorms + BM;
    float* en2s   = zinvs + BM;
    float* einvs  = en2s + BN;

    const int tid  = threadIdx.x;
    const int lane = tid & 31;
    const int warp = tid >> 5;
    const int t0   = warp * TT;

    unsigned smem_base;
    asm("{ .reg .u64 t; cvta.to.shared.u64 t, %1; cvt.u32.u64 %0, t; }"
        : "=r"(smem_base) : "l"((void*)smem));
    const unsigned zs_s = smem_base;
    const unsigned es_s = smem_base + BM * DP * 4;

    // ---- async-load z tile into padded rows ---------------------------
    {
        const float* zg = z + (size_t)blockIdx.x * BM * D;
#pragma unroll
        for (int idx = tid; idx < BM * (D / 4); idx += THREADS) {
            int q = idx & 15, r = idx >> 4;
            CP_ASYNC16(zs_s + (r * DP + 4 * q) * 4, zg + r * D + 4 * q);
        }
    }
    // ---- async-load first codebook chunk ------------------------------
#pragma unroll
    for (int idx = tid; idx < BN * (D / 4); idx += THREADS) {
        int q = idx & 15, c = idx >> 4;
        CP_ASYNC16(es_s + (c * DP + 4 * q) * 4, cbk + (size_t)c * D + 4 * q);
    }
    CP_COMMIT();
    CP_WAIT0();
    __syncthreads();

    // ---- per-token norms (conflict-free: padded rows) -----------------
    if (tid < BM) {
        float s = 0.f;
#pragma unroll
        for (int i = 0; i < D / 4; ++i) {
            float4 v = *reinterpret_cast<const float4*>(zs + tid * DP + 4 * i);
            s += v.x * v.x + v.y * v.y + v.z * v.z + v.w * v.w;
        }
        znorms[tid] = s;
        zinvs[tid]  = rsqrtf(s);
    }

    float mind[TT];
    int   mini[TT];
#pragma unroll
    for (int t = 0; t < TT; ++t) { mind[t] = 3.4e38f; mini[t] = 0; }

    const int nchunks = K / BN;
    for (int cbi = 0; cbi < nchunks; ++cbi) {
        if (tid < BN) {
            en2s[tid]  = g_en2[cbi * BN + tid];
            einvs[tid] = g_einv[cbi * BN + tid];
        }
        __syncthreads();

        // ---- main micro-kernel: 8 tokens x 4 codes per lane ----------
        unsigned long long acc[TT][TC];
#pragma unroll
        for (int t = 0; t < TT; ++t)
#pragma unroll
            for (int i = 0; i < TC; ++i) acc[t][i] = 0ull;

#pragma unroll
        for (int q = 0; q < D / 4; ++q) {
            // b: 4 conflict-free LDS.128 (code = lane + 32*i)
            unsigned long long blo[TC], bhi[TC];
#pragma unroll
            for (int i = 0; i < TC; ++i) {
                float4 b4 = *reinterpret_cast<const float4*>(es + (lane + 32 * i) * DP + 4 * q);
                blo[i] = pack2(b4.x, b4.y);
                bhi[i] = pack2(b4.z, b4.w);
            }
#pragma unroll
            for (int t = 0; t < TT; ++t) {
                float4 a4 = *reinterpret_cast<const float4*>(zs + (t0 + t) * DP + 4 * q); // broadcast
                unsigned long long alo = pack2(a4.x, a4.y);
                unsigned long long ahi = pack2(a4.z, a4.w);
#pragma unroll
                for (int i = 0; i < TC; ++i) {
                    FMA2(acc[t][i], alo, blo[i]);
                    FMA2(acc[t][i], ahi, bhi[i]);
                }
            }
        }

        // ---- epilogue: dist/argmin + fused coalesced sim writes ------
#pragma unroll
        for (int t = 0; t < TT; ++t) {
            float nzv = znorms[t0 + t];
            float ziv = zinvs[t0 + t];
            size_t row = ((size_t)blockIdx.x * BM + t0 + t) * (size_t)K + cbi * BN;
#pragma unroll
            for (int i = 0; i < TC; ++i) {
                int   cl  = lane + 32 * i;
                float2 p  = unpack2(acc[t][i]);
                float dot = p.x + p.y;
                float dist = nzv - 2.f * dot + en2s[cl];
                int   gc   = cbi * BN + cl;
                if (dist < mind[t] || (dist == mind[t] && gc < mini[t])) {
                    mind[t] = dist; mini[t] = gc;
                }
                __stcs(sim_out + row + cl, dot * ziv * einvs[cl]);   // 128B coalesced
            }
        }

        __syncthreads();   // compute done before refilling es

        // ---- prefetch next chunk --------------------------------------
        if (cbi + 1 < nchunks) {
            const float* base = cbk + (size_t)(cbi + 1) * BN * D;
#pragma unroll
            for (int idx = tid; idx < BN * (D / 4); idx += THREADS) {
                int q = idx & 15, c = idx >> 4;
                CP_ASYNC16(es_s + (c * DP + 4 * q) * 4, base + (size_t)c * D + 4 * q);
            }
            CP_COMMIT();
            CP_WAIT0();
        }
    }

    // ---- final: argmin across the warp, zq gather, loss ---------------
#pragma unroll
    for (int t = 0; t < TT; ++t) {
        float d  = mind[t];
        int   ix = mini[t];
#pragma unroll
        for (int off = 16; off; off >>= 1) {
            float od = __shfl_xor_sync(0xffffffffu, d, off);
            int   oi = __shfl_xor_sync(0xffffffffu, ix, off);
            if (od < d || (od == d && oi < ix)) { d = od; ix = oi; }
        }
        int    tl  = t0 + t;
        size_t tok = (size_t)blockIdx.x * BM + tl;

        float2 ev = reinterpret_cast<const float2*>(cbk + (size_t)ix * D)[lane];
        reinterpret_cast<float2*>(zq_out + tok * D)[lane] = ev;

        float zx = zs[tl * DP + 2 * lane], zy = zs[tl * DP + 2 * lane + 1];
        float dx = zx - ev.x, dy = zy - ev.y;
        float s = dx * dx + dy * dy;
#pragma unroll
        for (int off = 16; off; off >>= 1) s += __shfl_xor_sync(0xffffffffu, s, off);

        if (lane == 0) {
            loss_out[tok] = 1.25f * sqrtf(s);
            e_out[tok]    = (float)ix;
        }
    }
}

extern "C" void kernel_launch(void* const* d_in, const int* in_sizes, int n_in,
                              void* d_out, int out_size) {
    const float* z   = (const float*)d_in[0];
    const float* cbk = (const float*)d_in[1];
    const int NT = in_sizes[0] / D;
    const int K  = in_sizes[1] / D;

    float* out      = (float*)d_out;
    float* e_out    = out;
    float* zq_out   = e_out + NT;
    float* sim_out  = zq_out + (size_t)NT * D;
    float* loss_out = sim_out + (size_t)NT * K;

    vq_enorm_kernel<<<(K + 255) / 256, 256>>>(cbk, K);

    const size_t smem = (size_t)(BM * DP + BN * DP + BM + BM + BN + BN) * 4;
    cudaFuncSetAttribute(vq_main_kernel, cudaFuncAttributeMaxDynamicSharedMemorySize, (int)smem);
    vq_main_kernel<<<NT / BM, THREADS, smem>>>(z, cbk, K, e_out, zq_out, sim_out, loss_out);
}